// round 12
// baseline (speedup 1.0000x reference)
#include <cuda_runtime.h>
#include <cuda_bf16.h>
#include <math.h>
#include <cstdint>

#define NPTS  768
#define NHALF 384
#define DDIM  64
#define NPER  200
#define NKER  4
#define NSLOT 202     // 200 perms + identity(200) + all-ones(201)
#define PSLOTS 256    // padded p dimension (4 tiles of 64)
#define NTRI  300     // 24*25/2 triangle blocks of 32x32

#define INV_NN (1.0f/147072.0f)    // 384*383
#define INV_NM (1.0f/147456.0f)    // 384*384
#define C1 (2.0f*INV_NN + 2.0f*INV_NM)
#define C14 (0.25f*C1)
#define C4 (2.0f*INV_NM)
// 0.5*(1/nn - 1/nm), analytic (no cancellation)
#define CS ((float)(0.5*(1.0/147072.0 - 1.0/147456.0)))

// ---------------- scratch (device globals; zero-initialized) -------------
__device__ __nv_bfloat16 g_Khi[NKER][NPTS * NPTS];   // 4.5 MB
__device__ __nv_bfloat16 g_Kmd[NKER][NPTS * NPTS];   // 4.5 MB
__device__ uint32_t      g_Kpk[NKER][NPTS * NPTS];   // 9 MB (hi|md packed)
__device__ __nv_bfloat16 g_mbf[PSLOTS][NPTS];        // signed mask rows
__device__ float g_z[NKER][NHALF];                   // K[i][384+i] pre-zero value
__device__ float g_DtP[NKER][24];                    // diag partials per diag block
__device__ float g_part[NKER][24][PSLOTS];           // T partials (2 ksplit x 12 subtiles)

// ---------------- helpers ----------------
__device__ __forceinline__ float warpred(float v) {
    #pragma unroll
    for (int o = 16; o > 0; o >>= 1) v += __shfl_down_sync(0xffffffffu, v, o);
    return v;
}

__device__ __forceinline__ uint32_t s2u(const void* p) {
    uint32_t r;
    asm("{ .reg .u64 t; cvta.to.shared.u64 t, %1; cvt.u32.u64 %0, t; }"
        : "=r"(r) : "l"(p));
    return r;
}

// ---------------- kernel 1: mask (blocks 0..201) + symmetric pairK -------
// blocks 202..1401: (tri, k): tri = triangle tile (bi<=bj, 24x24 of 32x32),
// k = which of the 4 kernel functions. One kernel per block.
__global__ void __launch_bounds__(128) k_pairmask(const float* __restrict__ X,
                                                  const float* __restrict__ Y,
                                                  const float* __restrict__ bw,
                                                  const int* __restrict__ perms) {
    const int blk = blockIdx.x;
    const int tid = threadIdx.x;

    if (blk < NSLOT) {                      // ---- mask part ----
        const int p = blk;
        #pragma unroll
        for (int j = tid; j < NPTS; j += 128) {
            if (p < NPER) {
                g_mbf[p][perms[p * NPTS + j]] = __float2bfloat16(j < NHALF ? 1.f : -1.f);
            } else if (p == NPER) {
                g_mbf[p][j] = __float2bfloat16(j < NHALF ? 1.f : -1.f);
            } else {
                g_mbf[p][j] = __float2bfloat16(1.f);
            }
        }
        return;
    }

    // ---- (tri, k) decode ----
    const int idx0 = blk - NSLOT;
    const int k = idx0 / NTRI;              // kernel function 0..3
    int t = idx0 % NTRI, bi = 0;
    while (t >= 24 - bi) { t -= 24 - bi; bi++; }
    const int bj = bi + t;
    const int i0 = bi * 32, j0 = bj * 32;
    const bool diag = (bi == bj);

    __shared__ float Zi[32][65];
    __shared__ float Zj[32][65];
    __shared__ float sq[64];                 // sqi[0..31], sqj[32..63]
    __shared__ uint32_t smT[32][33];         // transpose staging
    __shared__ float dsh[4];

    for (int idx = tid; idx < 32 * 64; idx += 128) {
        int r = idx >> 6, d = idx & 63;
        int gi = i0 + r;
        Zi[r][d] = (gi < NHALF) ? X[gi * DDIM + d] : Y[(gi - NHALF) * DDIM + d];
        int gj = j0 + r;
        Zj[r][d] = (gj < NHALF) ? X[gj * DDIM + d] : Y[(gj - NHALF) * DDIM + d];
    }
    __syncthreads();

    if (tid < 64) {
        const float* src = (tid < 32) ? &Zi[tid][0] : &Zj[tid - 32][0];
        float s = 0.f;
        #pragma unroll
        for (int d = 0; d < 64; d++) { float v = src[d]; s += v * v; }
        sq[tid] = s;
    }
    __syncthreads();

    // 16x8 threads: ty=tid>>3 (16, rows x2), tx=tid&7 (8, cols x4)
    const int tx = tid & 7, ty = tid >> 3;
    float acc[2][4] = {};
    #pragma unroll 4
    for (int d = 0; d < 64; d++) {
        float a0 = Zi[ty * 2 + 0][d], a1 = Zi[ty * 2 + 1][d];
        float b0 = Zj[tx * 4 + 0][d], b1 = Zj[tx * 4 + 1][d];
        float b2 = Zj[tx * 4 + 2][d], b3 = Zj[tx * 4 + 3][d];
        acc[0][0] += a0 * b0; acc[0][1] += a0 * b1; acc[0][2] += a0 * b2; acc[0][3] += a0 * b3;
        acc[1][0] += a1 * b0; acc[1][1] += a1 * b1; acc[1][2] += a1 * b2; acc[1][3] += a1 * b3;
    }

    const float bwk = bw[k];
    const float iv = (k & 1) ? (1.f / bwk) : (1.f / (bwk * bwk));
    const bool lap = (k & 1);

    float dsum = 0.f;
    uint32_t pkU[2][4], pkD[2][4];
    #pragma unroll
    for (int ii = 0; ii < 2; ii++) {
        const int gi = i0 + ty * 2 + ii;
        const float si = sq[ty * 2 + ii];
        #pragma unroll
        for (int jj = 0; jj < 4; jj++) {
            const int gj = j0 + tx * 4 + jj;
            float d2 = si + sq[32 + tx * 4 + jj] - 2.f * acc[ii][jj];
            d2 = fmaxf(d2, 0.f);
            float dist = sqrtf(d2 + 1e-12f);
            float arg = lap ? (-dist * iv) : (-dist * dist * iv);
            float kv = __expf(arg);
            bool zr = (gi < NHALF) && (gj == gi + NHALF);
            if (zr) g_z[k][gi] = kv;
            if (gi == gj) dsum += kv;
            __nv_bfloat16 h = __float2bfloat16(kv);
            __nv_bfloat16 m = __float2bfloat16(kv - __bfloat162float(h));
            __nv_bfloat162 pr(h, m);
            uint32_t u = *(uint32_t*)&pr;
            pkU[ii][jj] = u;
            pkD[ii][jj] = zr ? 0u : u;
        }
    }

    // direct tile writes (zeroed where required)
    #pragma unroll
    for (int ii = 0; ii < 2; ii++) {
        const size_t base = (size_t)(i0 + ty * 2 + ii) * NPTS + j0 + tx * 4;
        uint2 hv, mv;
        hv.x = __byte_perm(pkD[ii][0], pkD[ii][1], 0x5410);
        hv.y = __byte_perm(pkD[ii][2], pkD[ii][3], 0x5410);
        mv.x = __byte_perm(pkD[ii][0], pkD[ii][1], 0x7632);
        mv.y = __byte_perm(pkD[ii][2], pkD[ii][3], 0x7632);
        *(uint2*)&g_Khi[k][base] = hv;
        *(uint2*)&g_Kmd[k][base] = mv;
        *(uint4*)&g_Kpk[k][base] = make_uint4(pkD[ii][0], pkD[ii][1],
                                              pkD[ii][2], pkD[ii][3]);
    }

    // mirrored tile (un-zeroed) via smem transpose
    if (!diag) {
        #pragma unroll
        for (int ii = 0; ii < 2; ii++) {
            #pragma unroll
            for (int jj = 0; jj < 4; jj++)
                smT[ty * 2 + ii][tx * 4 + jj] = pkU[ii][jj];
        }
        __syncthreads();
        const int rr = tid >> 2;             // 0..31 = original column index
        const int cc0 = (tid & 3) * 8;       // 8 consecutive original rows
        uint32_t v[8];
        #pragma unroll
        for (int q = 0; q < 8; q++) v[q] = smT[cc0 + q][rr];
        const size_t base = (size_t)(j0 + rr) * NPTS + i0 + cc0;
        uint2 hv0, hv1, mv0, mv1;
        hv0.x = __byte_perm(v[0], v[1], 0x5410);
        hv0.y = __byte_perm(v[2], v[3], 0x5410);
        hv1.x = __byte_perm(v[4], v[5], 0x5410);
        hv1.y = __byte_perm(v[6], v[7], 0x5410);
        mv0.x = __byte_perm(v[0], v[1], 0x7632);
        mv0.y = __byte_perm(v[2], v[3], 0x7632);
        mv1.x = __byte_perm(v[4], v[5], 0x7632);
        mv1.y = __byte_perm(v[6], v[7], 0x7632);
        *(uint2*)&g_Khi[k][base]     = hv0;
        *(uint2*)&g_Khi[k][base + 4] = hv1;
        *(uint2*)&g_Kmd[k][base]     = mv0;
        *(uint2*)&g_Kmd[k][base + 4] = mv1;
        *(uint4*)&g_Kpk[k][base]     = make_uint4(v[0], v[1], v[2], v[3]);
        *(uint4*)&g_Kpk[k][base + 4] = make_uint4(v[4], v[5], v[6], v[7]);
    } else {
        // diag blocks: deterministic reduce of diagonal sums
        const int w = tid >> 5, lane = tid & 31;
        float v = warpred(dsum);
        if (lane == 0) dsh[w] = v;
        __syncthreads();
        if (tid == 0)
            g_DtP[k][bi] = dsh[0] + dsh[1] + dsh[2] + dsh[3];
    }
}

// ---------------- kernel 2: mma.sync signed GEMM -> T partials -----------
// grid (6 n-tiles, 4 p-tiles, kk*2+ksplit); 256 threads (8 warps: 4m x 2n).
__global__ void __launch_bounds__(256) k_mma() {
    __shared__ __align__(16) unsigned char As[2][64 * 128];    // 16 KB
    __shared__ __align__(16) unsigned char Bs[2][128 * 128];   // 32 KB
    const int nt = blockIdx.x, pt = blockIdx.y;
    const int kk = blockIdx.z >> 1, ks = blockIdx.z & 1;
    const int tid = threadIdx.x, w = tid >> 5, lane = tid & 31;
    const int wm = w & 3, wn = w >> 2;
    const uint32_t aBase = s2u(&As[0][0]);
    const uint32_t bBase = s2u(&Bs[0][0]);
    const __nv_bfloat16* __restrict__ KP = ks ? g_Kmd[kk] : g_Khi[kk];

    float d[8][4] = {};

    auto load = [&](int ch, int buf) {
        const int a0 = ch * 64;
        #pragma unroll 2
        for (int idx = tid; idx < 512; idx += 256) {        // A: 64 rows x 128B
            int r = idx >> 3, c = idx & 7;
            uint4 v = *(const uint4*)&g_mbf[pt * 64 + r][a0 + c * 8];
            *(uint4*)&As[buf][r * 128 + ((c ^ (r & 7)) << 4)] = v;
        }
        #pragma unroll 4
        for (int idx = tid; idx < 1024; idx += 256) {       // B: 128 rows x 128B
            int r = idx >> 3, c = idx & 7;
            uint4 v = *(const uint4*)&KP[(size_t)(nt * 128 + r) * NPTS + a0 + c * 8];
            *(uint4*)&Bs[buf][r * 128 + ((c ^ (r & 7)) << 4)] = v;
        }
    };

    load(0, 0);
    __syncthreads();
    for (int ch = 0; ch < 12; ch++) {
        const int buf = ch & 1;
        if (ch + 1 < 12) load(ch + 1, buf ^ 1);
        #pragma unroll
        for (int ksq = 0; ksq < 4; ksq++) {
            uint32_t a[4];
            {
                int r = wm * 16 + (lane & 15);
                int c = ksq * 2 + (lane >> 4);
                uint32_t addr = aBase + buf * 8192 + r * 128 + ((c ^ (r & 7)) << 4);
                asm volatile("ldmatrix.sync.aligned.m8n8.x4.shared.b16 {%0,%1,%2,%3}, [%4];"
                             : "=r"(a[0]), "=r"(a[1]), "=r"(a[2]), "=r"(a[3]) : "r"(addr));
            }
            #pragma unroll
            for (int j = 0; j < 8; j++) {
                uint32_t b[2];
                int r = wn * 64 + j * 8 + (lane & 7);
                int c = ksq * 2 + ((lane >> 3) & 1);
                uint32_t addr = bBase + buf * 16384 + r * 128 + ((c ^ (r & 7)) << 4);
                asm volatile("ldmatrix.sync.aligned.m8n8.x2.shared.b16 {%0,%1}, [%2];"
                             : "=r"(b[0]), "=r"(b[1]) : "r"(addr));
                asm volatile("mma.sync.aligned.m16n8k16.row.col.f32.bf16.bf16.f32 "
                             "{%0,%1,%2,%3}, {%4,%5,%6,%7}, {%8,%9}, {%0,%1,%2,%3};"
                             : "+f"(d[j][0]), "+f"(d[j][1]), "+f"(d[j][2]), "+f"(d[j][3])
                             : "r"(a[0]), "r"(a[1]), "r"(a[2]), "r"(a[3]),
                               "r"(b[0]), "r"(b[1]));
            }
        }
        __syncthreads();
    }

    // epilogue: partial T[p] = sum_b s[p][b] * D'[p][b]
    const int lq = lane >> 2, lr = lane & 3;
    const int p0 = pt * 64 + wm * 16 + lq;
    const int p1 = p0 + 8;
    float part0 = 0.f, part1 = 0.f;
    #pragma unroll
    for (int j = 0; j < 8; j++) {
        int b0 = nt * 128 + wn * 64 + j * 8 + lr * 2;
        float m0 = __bfloat162float(g_mbf[p0][b0]);
        float m1 = __bfloat162float(g_mbf[p0][b0 + 1]);
        part0 += d[j][0] * m0 + d[j][1] * m1;
        float n0 = __bfloat162float(g_mbf[p1][b0]);
        float n1 = __bfloat162float(g_mbf[p1][b0 + 1]);
        part1 += d[j][2] * n0 + d[j][3] * n1;
    }
    part0 += __shfl_xor_sync(0xffffffffu, part0, 1);
    part0 += __shfl_xor_sync(0xffffffffu, part0, 2);
    part1 += __shfl_xor_sync(0xffffffffu, part1, 1);
    part1 += __shfl_xor_sync(0xffffffffu, part1, 2);
    if (lr == 0) {
        const int sub = ks * 12 + nt * 2 + wn;
        g_part[kk][sub][p0] = part0;
        g_part[kk][sub][p1] = part1;
    }
}

// ---------------- kernel 3: phase 2 per-(slot, kernel) combine -----------
// Ub = (C1/4)*T + sum_{a in A} (+-z[a])/nm + C4*cross + (S*CS - Dt/nn)
__global__ void __launch_bounds__(128) k_phase2(const int* __restrict__ perms,
                                                float* __restrict__ out) {
    const int p = blockIdx.x;          // 0..200
    const int kk = blockIdx.y;
    const int tid = threadIdx.x;       // 128
    __shared__ float sm[3][4];
    const bool ident = (p == NPER);

    const uint32_t* __restrict__ Kp = g_Kpk[kk];
    const float* __restrict__ Zc = g_z[kk];

    float t1 = 0.f, cr = 0.f, aux = 0.f;
    #pragma unroll
    for (int it = 0; it < 3; it++) {
        int j = tid + it * 128;
        int a = ident ? j : __ldg(&perms[p * NPTS + j]);
        int b = ident ? (NHALF + j) : __ldg(&perms[p * NPTS + NHALF + j]);
        t1 += (a < NHALF) ? (INV_NM * Zc[a]) : (-INV_NM * Zc[a - NHALF]);
        uint32_t wv = __ldg(&Kp[a * NPTS + b]);
        __nv_bfloat162 v = *reinterpret_cast<__nv_bfloat162*>(&wv);
        cr += __bfloat162float(v.x) + __bfloat162float(v.y);
    }
    if (tid < 24) {
        t1 += C14 * g_part[kk][tid][p];
        aux += CS * g_part[kk][tid][201];          // S*CS partials
    }
    if (tid >= 32 && tid < 56)
        aux -= INV_NN * g_DtP[kk][tid - 32];       // -Dt/nn partials

    float r1 = warpred(t1), r2 = warpred(cr), r3 = warpred(aux);
    if ((tid & 31) == 0) {
        sm[0][tid >> 5] = r1; sm[1][tid >> 5] = r2; sm[2][tid >> 5] = r3;
    }
    __syncthreads();
    if (tid == 0) {
        float T1 = sm[0][0] + sm[0][1] + sm[0][2] + sm[0][3];
        float CR = sm[1][0] + sm[1][1] + sm[1][2] + sm[1][3];
        float AX = sm[2][0] + sm[2][1] + sm[2][2] + sm[2][3];
        float Ub = T1 + C4 * CR + AX;
        int idx = ident ? (kk * (NPER + 1)) : (kk * (NPER + 1) + 1 + p);
        out[idx] = Ub;
    }
}

// ---------------- launch ----------------
extern "C" void kernel_launch(void* const* d_in, const int* in_sizes, int n_in,
                              void* d_out, int out_size) {
    const float* X     = (const float*)d_in[0];
    const float* Y     = (const float*)d_in[1];
    const float* bw    = (const float*)d_in[2];
    const int*   perms = (const int*)d_in[3];
    float* out = (float*)d_out;

    k_pairmask<<<NSLOT + NTRI * NKER, 128>>>(X, Y, bw, perms);
    k_mma<<<dim3(6, 4, 8), 256>>>();
    k_phase2<<<dim3(NPER + 1, NKER), 128>>>(perms, out);
}

// round 14
// speedup vs baseline: 1.2183x; 1.2183x over previous
#include <cuda_runtime.h>
#include <cuda_bf16.h>
#include <math.h>
#include <cstdint>

#define NPTS  768
#define NHALF 384
#define DDIM  64
#define NPER  200
#define NKER  4
#define NSLOT 202     // 200 perms + identity(200) + all-ones(201)
#define PSLOTS 256    // padded p dimension (4 tiles of 64)
#define NTRI  300     // 24*25/2 triangle blocks of 32x32

#define INV_NN (1.0f/147072.0f)    // 384*383
#define INV_NM (1.0f/147456.0f)    // 384*384
#define C1 (2.0f*INV_NN + 2.0f*INV_NM)
#define C14 (0.25f*C1)
#define C4 (2.0f*INV_NM)
// 0.5*(1/nn - 1/nm), analytic (no cancellation)
#define CS ((float)(0.5*(1.0/147072.0 - 1.0/147456.0)))

// ---------------- scratch (device globals; zero-initialized) -------------
__device__ __nv_bfloat16 g_Khi[NKER][NPTS * NPTS];   // 4.5 MB
__device__ __nv_bfloat16 g_Kmd[NKER][NPTS * NPTS];   // 4.5 MB
__device__ uint32_t      g_Kpk[NKER][NPTS * NPTS];   // 9 MB (hi|md packed)
__device__ __nv_bfloat16 g_mbf[PSLOTS][NPTS];        // signed mask rows
__device__ float g_z[NKER][NHALF];                   // K[i][384+i] pre-zero value
__device__ float g_DtP[NKER][24];                    // diag partials per diag block
__device__ float g_part[NKER][24][PSLOTS];           // T partials (2 ksplit x 12 subtiles)

// ---------------- helpers ----------------
__device__ __forceinline__ float warpred(float v) {
    #pragma unroll
    for (int o = 16; o > 0; o >>= 1) v += __shfl_down_sync(0xffffffffu, v, o);
    return v;
}

__device__ __forceinline__ uint32_t s2u(const void* p) {
    uint32_t r;
    asm("{ .reg .u64 t; cvta.to.shared.u64 t, %1; cvt.u32.u64 %0, t; }"
        : "=r"(r) : "l"(p));
    return r;
}

// ---------------- kernel 1: mask (blocks 0..201) + symmetric pairK -------
// triangle blocks 202..501: one 32x32 tile, ALL 4 kernel fns via warp groups.
__global__ void __launch_bounds__(512) k_pairmask(const float* __restrict__ X,
                                                  const float* __restrict__ Y,
                                                  const float* __restrict__ bw,
                                                  const int* __restrict__ perms) {
    const int blk = blockIdx.x;
    const int tid = threadIdx.x;

    if (blk < NSLOT) {                      // ---- mask part ----
        const int p = blk;
        for (int j = tid; j < NPTS; j += 512) {
            if (p < NPER) {
                g_mbf[p][perms[p * NPTS + j]] = __float2bfloat16(j < NHALF ? 1.f : -1.f);
            } else if (p == NPER) {
                g_mbf[p][j] = __float2bfloat16(j < NHALF ? 1.f : -1.f);
            } else {
                g_mbf[p][j] = __float2bfloat16(1.f);
            }
        }
        return;
    }

    // ---- triangle decode ----
    int t2 = blk - NSLOT, bi = 0;
    while (t2 >= 24 - bi) { t2 -= 24 - bi; bi++; }
    const int bj = bi + t2;
    const int i0 = bi * 32, j0 = bj * 32;
    const bool diag = (bi == bj);

    // 68-float row stride: 272B per row -> every float4 slot 16B-aligned
    __shared__ float Zi[32][68];
    __shared__ float Zj[32][68];
    __shared__ float sq[64];                 // sqi[0..31], sqj[32..63]
    __shared__ float dsm[32][33];            // distances
    __shared__ float dsh[4][4];              // diag partials [group][warp]

    // load Z tiles (float4 vectorized; 512 threads = 32 rows x 16 quads)
    {
        const int r = tid >> 4, q = tid & 15;
        const int gi = i0 + r;
        const float4* srcI = (const float4*)((gi < NHALF) ? (X + gi * DDIM)
                                                          : (Y + (gi - NHALF) * DDIM));
        *(float4*)&Zi[r][q * 4] = srcI[q];
        const int gj = j0 + r;
        const float4* srcJ = (const float4*)((gj < NHALF) ? (X + gj * DDIM)
                                                          : (Y + (gj - NHALF) * DDIM));
        *(float4*)&Zj[r][q * 4] = srcJ[q];
    }
    __syncthreads();

    if (tid < 64) {
        const float* src = (tid < 32) ? &Zi[tid][0] : &Zj[tid - 32][0];
        float s = 0.f;
        #pragma unroll
        for (int d = 0; d < 64; d++) { float v = src[d]; s += v * v; }
        sq[tid] = s;
    }
    __syncthreads();

    // dot phase: 512 threads, each 2 elements (row dty; cols dtx, dtx+16)
    {
        const int dty = tid >> 4, dtx = tid & 15;
        float acc0 = 0.f, acc1 = 0.f;
        #pragma unroll
        for (int q = 0; q < 16; q++) {
            float4 a  = *(const float4*)&Zi[dty][q * 4];
            float4 b0 = *(const float4*)&Zj[dtx][q * 4];
            float4 b1 = *(const float4*)&Zj[dtx + 16][q * 4];
            acc0 += a.x * b0.x + a.y * b0.y + a.z * b0.z + a.w * b0.w;
            acc1 += a.x * b1.x + a.y * b1.y + a.z * b1.z + a.w * b1.w;
        }
        float si = sq[dty];
        float d20 = fmaxf(si + sq[32 + dtx] - 2.f * acc0, 0.f);
        float d21 = fmaxf(si + sq[32 + dtx + 16] - 2.f * acc1, 0.f);
        dsm[dty][dtx]      = sqrtf(d20 + 1e-12f);
        dsm[dty][dtx + 16] = sqrtf(d21 + 1e-12f);
    }
    __syncthreads();

    // kernel phase: group g (128 threads) handles kernel function g
    const int k = tid >> 7;                  // 0..3
    const int t = tid & 127;
    const float bwk = bw[k];
    const float iv = (k & 1) ? (1.f / bwk) : (1.f / (bwk * bwk));
    const bool lap = (k & 1);

    const int tx = t & 7, ty = t >> 3;
    float dsum = 0.f;
    // direct tile (zeroed where required)
    #pragma unroll
    for (int ii = 0; ii < 2; ii++) {
        const int lr = ty * 2 + ii;
        const int gi = i0 + lr;
        uint32_t pk[4];
        #pragma unroll
        for (int jj = 0; jj < 4; jj++) {
            const int lc = tx * 4 + jj;
            const int gj = j0 + lc;
            float dist = dsm[lr][lc];
            float kv = __expf(lap ? (-dist * iv) : (-dist * dist * iv));
            bool zr = (gi < NHALF) && (gj == gi + NHALF);
            if (zr) g_z[k][gi] = kv;
            if (gi == gj) dsum += kv;
            __nv_bfloat16 h = __float2bfloat16(kv);
            __nv_bfloat16 m = __float2bfloat16(kv - __bfloat162float(h));
            __nv_bfloat162 pr(h, m);
            uint32_t u = *(uint32_t*)&pr;
            pk[jj] = zr ? 0u : u;
        }
        const size_t base = (size_t)gi * NPTS + j0 + tx * 4;
        uint2 hv, mv;
        hv.x = __byte_perm(pk[0], pk[1], 0x5410);
        hv.y = __byte_perm(pk[2], pk[3], 0x5410);
        mv.x = __byte_perm(pk[0], pk[1], 0x7632);
        mv.y = __byte_perm(pk[2], pk[3], 0x7632);
        *(uint2*)&g_Khi[k][base] = hv;
        *(uint2*)&g_Kmd[k][base] = mv;
        *(uint4*)&g_Kpk[k][base] = make_uint4(pk[0], pk[1], pk[2], pk[3]);
    }

    if (!diag) {
        // mirrored tile (un-zeroed): output row j0+rr, cols i0+cc0..+7
        const int rr = t >> 2;               // original column index 0..31
        const int cc0 = (t & 3) * 8;         // 8 consecutive original rows
        uint32_t v[8];
        #pragma unroll
        for (int q = 0; q < 8; q++) {
            float dist = dsm[cc0 + q][rr];
            float kv = __expf(lap ? (-dist * iv) : (-dist * dist * iv));
            __nv_bfloat16 h = __float2bfloat16(kv);
            __nv_bfloat16 m = __float2bfloat16(kv - __bfloat162float(h));
            __nv_bfloat162 pr(h, m);
            v[q] = *(uint32_t*)&pr;
        }
        const size_t base = (size_t)(j0 + rr) * NPTS + i0 + cc0;
        uint2 hv0, hv1, mv0, mv1;
        hv0.x = __byte_perm(v[0], v[1], 0x5410);
        hv0.y = __byte_perm(v[2], v[3], 0x5410);
        hv1.x = __byte_perm(v[4], v[5], 0x5410);
        hv1.y = __byte_perm(v[6], v[7], 0x5410);
        mv0.x = __byte_perm(v[0], v[1], 0x7632);
        mv0.y = __byte_perm(v[2], v[3], 0x7632);
        mv1.x = __byte_perm(v[4], v[5], 0x7632);
        mv1.y = __byte_perm(v[6], v[7], 0x7632);
        *(uint2*)&g_Khi[k][base]     = hv0;
        *(uint2*)&g_Khi[k][base + 4] = hv1;
        *(uint2*)&g_Kmd[k][base]     = mv0;
        *(uint2*)&g_Kmd[k][base + 4] = mv1;
        *(uint4*)&g_Kpk[k][base]     = make_uint4(v[0], v[1], v[2], v[3]);
        *(uint4*)&g_Kpk[k][base + 4] = make_uint4(v[4], v[5], v[6], v[7]);
    } else {
        float v = warpred(dsum);
        if ((t & 31) == 0) dsh[k][t >> 5] = v;
    }
    __syncthreads();
    if (diag && t == 0)
        g_DtP[k][bi] = dsh[k][0] + dsh[k][1] + dsh[k][2] + dsh[k][3];
}

// ---------------- kernel 2: mma.sync signed GEMM -> T partials -----------
// grid (6 n-tiles, 4 p-tiles, kk*2+ksplit); 256 threads (8 warps: 4m x 2n).
__global__ void __launch_bounds__(256) k_mma() {
    __shared__ __align__(16) unsigned char As[2][64 * 128];    // 16 KB
    __shared__ __align__(16) unsigned char Bs[2][128 * 128];   // 32 KB
    const int nt = blockIdx.x, pt = blockIdx.y;
    const int kk = blockIdx.z >> 1, ks = blockIdx.z & 1;
    const int tid = threadIdx.x, w = tid >> 5, lane = tid & 31;
    const int wm = w & 3, wn = w >> 2;
    const uint32_t aBase = s2u(&As[0][0]);
    const uint32_t bBase = s2u(&Bs[0][0]);
    const __nv_bfloat16* __restrict__ KP = ks ? g_Kmd[kk] : g_Khi[kk];

    float d[8][4] = {};

    auto load = [&](int ch, int buf) {
        const int a0 = ch * 64;
        #pragma unroll 2
        for (int idx = tid; idx < 512; idx += 256) {        // A: 64 rows x 128B
            int r = idx >> 3, c = idx & 7;
            uint4 v = *(const uint4*)&g_mbf[pt * 64 + r][a0 + c * 8];
            *(uint4*)&As[buf][r * 128 + ((c ^ (r & 7)) << 4)] = v;
        }
        #pragma unroll 4
        for (int idx = tid; idx < 1024; idx += 256) {       // B: 128 rows x 128B
            int r = idx >> 3, c = idx & 7;
            uint4 v = *(const uint4*)&KP[(size_t)(nt * 128 + r) * NPTS + a0 + c * 8];
            *(uint4*)&Bs[buf][r * 128 + ((c ^ (r & 7)) << 4)] = v;
        }
    };

    load(0, 0);
    __syncthreads();
    for (int ch = 0; ch < 12; ch++) {
        const int buf = ch & 1;
        if (ch + 1 < 12) load(ch + 1, buf ^ 1);
        #pragma unroll
        for (int ksq = 0; ksq < 4; ksq++) {
            uint32_t a[4];
            {
                int r = wm * 16 + (lane & 15);
                int c = ksq * 2 + (lane >> 4);
                uint32_t addr = aBase + buf * 8192 + r * 128 + ((c ^ (r & 7)) << 4);
                asm volatile("ldmatrix.sync.aligned.m8n8.x4.shared.b16 {%0,%1,%2,%3}, [%4];"
                             : "=r"(a[0]), "=r"(a[1]), "=r"(a[2]), "=r"(a[3]) : "r"(addr));
            }
            #pragma unroll
            for (int j = 0; j < 8; j++) {
                uint32_t b[2];
                int r = wn * 64 + j * 8 + (lane & 7);
                int c = ksq * 2 + ((lane >> 3) & 1);
                uint32_t addr = bBase + buf * 16384 + r * 128 + ((c ^ (r & 7)) << 4);
                asm volatile("ldmatrix.sync.aligned.m8n8.x2.shared.b16 {%0,%1}, [%2];"
                             : "=r"(b[0]), "=r"(b[1]) : "r"(addr));
                asm volatile("mma.sync.aligned.m16n8k16.row.col.f32.bf16.bf16.f32 "
                             "{%0,%1,%2,%3}, {%4,%5,%6,%7}, {%8,%9}, {%0,%1,%2,%3};"
                             : "+f"(d[j][0]), "+f"(d[j][1]), "+f"(d[j][2]), "+f"(d[j][3])
                             : "r"(a[0]), "r"(a[1]), "r"(a[2]), "r"(a[3]),
                               "r"(b[0]), "r"(b[1]));
            }
        }
        __syncthreads();
    }

    // epilogue: partial T[p] = sum_b s[p][b] * D'[p][b]
    const int lq = lane >> 2, lr = lane & 3;
    const int p0 = pt * 64 + wm * 16 + lq;
    const int p1 = p0 + 8;
    float part0 = 0.f, part1 = 0.f;
    #pragma unroll
    for (int j = 0; j < 8; j++) {
        int b0 = nt * 128 + wn * 64 + j * 8 + lr * 2;
        float m0 = __bfloat162float(g_mbf[p0][b0]);
        float m1 = __bfloat162float(g_mbf[p0][b0 + 1]);
        part0 += d[j][0] * m0 + d[j][1] * m1;
        float n0 = __bfloat162float(g_mbf[p1][b0]);
        float n1 = __bfloat162float(g_mbf[p1][b0 + 1]);
        part1 += d[j][2] * n0 + d[j][3] * n1;
    }
    part0 += __shfl_xor_sync(0xffffffffu, part0, 1);
    part0 += __shfl_xor_sync(0xffffffffu, part0, 2);
    part1 += __shfl_xor_sync(0xffffffffu, part1, 1);
    part1 += __shfl_xor_sync(0xffffffffu, part1, 2);
    if (lr == 0) {
        const int sub = ks * 12 + nt * 2 + wn;
        g_part[kk][sub][p0] = part0;
        g_part[kk][sub][p1] = part1;
    }
}

// ---------------- kernel 3: phase 2 per-(slot, kernel) combine -----------
// Ub = (C1/4)*T + sum_{a in A} (+-z[a])/nm + C4*cross + (S*CS - Dt/nn)
__global__ void __launch_bounds__(128) k_phase2(const int* __restrict__ perms,
                                                float* __restrict__ out) {
    const int p = blockIdx.x;          // 0..200
    const int kk = blockIdx.y;
    const int tid = threadIdx.x;       // 128
    __shared__ float sm[3][4];
    const bool ident = (p == NPER);

    const uint32_t* __restrict__ Kp = g_Kpk[kk];
    const float* __restrict__ Zc = g_z[kk];

    float t1 = 0.f, cr = 0.f, aux = 0.f;
    #pragma unroll
    for (int it = 0; it < 3; it++) {
        int j = tid + it * 128;
        int a = ident ? j : __ldg(&perms[p * NPTS + j]);
        int b = ident ? (NHALF + j) : __ldg(&perms[p * NPTS + NHALF + j]);
        t1 += (a < NHALF) ? (INV_NM * Zc[a]) : (-INV_NM * Zc[a - NHALF]);
        uint32_t wv = __ldg(&Kp[a * NPTS + b]);
        __nv_bfloat162 v = *reinterpret_cast<__nv_bfloat162*>(&wv);
        cr += __bfloat162float(v.x) + __bfloat162float(v.y);
    }
    if (tid < 24) {
        t1 += C14 * g_part[kk][tid][p];
        aux += CS * g_part[kk][tid][201];          // S*CS partials
    }
    if (tid >= 32 && tid < 56)
        aux -= INV_NN * g_DtP[kk][tid - 32];       // -Dt/nn partials

    float r1 = warpred(t1), r2 = warpred(cr), r3 = warpred(aux);
    if ((tid & 31) == 0) {
        sm[0][tid >> 5] = r1; sm[1][tid >> 5] = r2; sm[2][tid >> 5] = r3;
    }
    __syncthreads();
    if (tid == 0) {
        float T1 = sm[0][0] + sm[0][1] + sm[0][2] + sm[0][3];
        float CR = sm[1][0] + sm[1][1] + sm[1][2] + sm[1][3];
        float AX = sm[2][0] + sm[2][1] + sm[2][2] + sm[2][3];
        float Ub = T1 + C4 * CR + AX;
        int idx = ident ? (kk * (NPER + 1)) : (kk * (NPER + 1) + 1 + p);
        out[idx] = Ub;
    }
}

// ---------------- launch ----------------
extern "C" void kernel_launch(void* const* d_in, const int* in_sizes, int n_in,
                              void* d_out, int out_size) {
    const float* X     = (const float*)d_in[0];
    const float* Y     = (const float*)d_in[1];
    const float* bw    = (const float*)d_in[2];
    const int*   perms = (const int*)d_in[3];
    float* out = (float*)d_out;

    k_pairmask<<<NSLOT + NTRI, 512>>>(X, Y, bw, perms);
    k_mma<<<dim3(6, 4, 8), 256>>>();
    k_phase2<<<dim3(NPER + 1, NKER), 128>>>(perms, out);
}

// round 15
// speedup vs baseline: 1.2970x; 1.0646x over previous
#include <cuda_runtime.h>
#include <cuda_bf16.h>
#include <math.h>
#include <cstdint>

#define NPTS  768
#define NPTS2 1536    // doubled-k (hi,md interleaved)
#define NHALF 384
#define DDIM  64
#define NPER  200
#define NKER  4
#define NSLOT 202     // 200 perms + identity(200) + all-ones(201)
#define PSLOTS 256    // padded p dimension (4 tiles of 64)
#define NTRI  300     // 24*25/2 triangle blocks of 32x32

#define INV_NN (1.0f/147072.0f)    // 384*383
#define INV_NM (1.0f/147456.0f)    // 384*384
#define C1 (2.0f*INV_NN + 2.0f*INV_NM)
#define C14 (0.25f*C1)
#define C4 (2.0f*INV_NM)
// 0.5*(1/nn - 1/nm), analytic (no cancellation)
#define CS ((float)(0.5*(1.0/147072.0 - 1.0/147456.0)))

// ---------------- scratch (device globals; zero-initialized) -------------
__device__ uint32_t      g_Kpk[NKER][NPTS * NPTS];   // 9 MB: (hi,md) bf16 pairs
__device__ __nv_bfloat16 g_mbf[PSLOTS][NPTS];        // signed mask rows
__device__ __nv_bfloat16 g_mbf2[PSLOTS][NPTS2];      // duplicated mask (doubled-k)
__device__ float g_z[NKER][NHALF];                   // K[i][384+i] pre-zero value
__device__ float g_DtP[NKER][24];                    // diag partials per diag block
__device__ float g_part[NKER][48][PSLOTS];           // T partials (4 kquarter x 12 subtiles)

// ---------------- helpers ----------------
__device__ __forceinline__ float warpred(float v) {
    #pragma unroll
    for (int o = 16; o > 0; o >>= 1) v += __shfl_down_sync(0xffffffffu, v, o);
    return v;
}

__device__ __forceinline__ uint32_t s2u(const void* p) {
    uint32_t r;
    asm("{ .reg .u64 t; cvta.to.shared.u64 t, %1; cvt.u32.u64 %0, t; }"
        : "=r"(r) : "l"(p));
    return r;
}

// ---------------- kernel 1: mask (blocks 0..201) + symmetric pairK -------
// triangle blocks 202..501: one 32x32 tile, ALL 4 kernel fns via warp groups.
__global__ void __launch_bounds__(512) k_pairmask(const float* __restrict__ X,
                                                  const float* __restrict__ Y,
                                                  const float* __restrict__ bw,
                                                  const int* __restrict__ perms) {
    const int blk = blockIdx.x;
    const int tid = threadIdx.x;

    if (blk < NSLOT) {                      // ---- mask part ----
        const int p = blk;
        for (int j = tid; j < NPTS; j += 512) {
            __nv_bfloat16 v;
            int a;
            if (p < NPER) {
                v = __float2bfloat16(j < NHALF ? 1.f : -1.f);
                a = perms[p * NPTS + j];
            } else if (p == NPER) {
                v = __float2bfloat16(j < NHALF ? 1.f : -1.f);
                a = j;
            } else {
                v = __float2bfloat16(1.f);
                a = j;
            }
            g_mbf[p][a] = v;
            __nv_bfloat162 vv(v, v);
            *(__nv_bfloat162*)&g_mbf2[p][2 * a] = vv;
        }
        return;
    }

    // ---- triangle decode ----
    int t2 = blk - NSLOT, bi = 0;
    while (t2 >= 24 - bi) { t2 -= 24 - bi; bi++; }
    const int bj = bi + t2;
    const int i0 = bi * 32, j0 = bj * 32;
    const bool diag = (bi == bj);

    // 68-float row stride: 272B per row -> every float4 slot 16B-aligned
    __shared__ float Zi[32][68];
    __shared__ float Zj[32][68];
    __shared__ float sq[64];                 // sqi[0..31], sqj[32..63]
    __shared__ float dsm[32][33];            // distances
    __shared__ float dsh[4][4];              // diag partials [group][warp]

    // load Z tiles (float4 vectorized; 512 threads = 32 rows x 16 quads)
    {
        const int r = tid >> 4, q = tid & 15;
        const int gi = i0 + r;
        const float4* srcI = (const float4*)((gi < NHALF) ? (X + gi * DDIM)
                                                          : (Y + (gi - NHALF) * DDIM));
        *(float4*)&Zi[r][q * 4] = srcI[q];
        const int gj = j0 + r;
        const float4* srcJ = (const float4*)((gj < NHALF) ? (X + gj * DDIM)
                                                          : (Y + (gj - NHALF) * DDIM));
        *(float4*)&Zj[r][q * 4] = srcJ[q];
    }
    __syncthreads();

    if (tid < 64) {
        const float* src = (tid < 32) ? &Zi[tid][0] : &Zj[tid - 32][0];
        float s = 0.f;
        #pragma unroll
        for (int d = 0; d < 64; d++) { float v = src[d]; s += v * v; }
        sq[tid] = s;
    }
    __syncthreads();

    // dot phase: 512 threads, each 2 elements (row dty; cols dtx, dtx+16)
    {
        const int dty = tid >> 4, dtx = tid & 15;
        float acc0 = 0.f, acc1 = 0.f;
        #pragma unroll
        for (int q = 0; q < 16; q++) {
            float4 a  = *(const float4*)&Zi[dty][q * 4];
            float4 b0 = *(const float4*)&Zj[dtx][q * 4];
            float4 b1 = *(const float4*)&Zj[dtx + 16][q * 4];
            acc0 += a.x * b0.x + a.y * b0.y + a.z * b0.z + a.w * b0.w;
            acc1 += a.x * b1.x + a.y * b1.y + a.z * b1.z + a.w * b1.w;
        }
        float si = sq[dty];
        float d20 = fmaxf(si + sq[32 + dtx] - 2.f * acc0, 0.f);
        float d21 = fmaxf(si + sq[32 + dtx + 16] - 2.f * acc1, 0.f);
        dsm[dty][dtx]      = sqrtf(d20 + 1e-12f);
        dsm[dty][dtx + 16] = sqrtf(d21 + 1e-12f);
    }
    __syncthreads();

    // kernel phase: group g (128 threads) handles kernel function g
    const int k = tid >> 7;                  // 0..3
    const int t = tid & 127;
    const float bwk = bw[k];
    const float iv = (k & 1) ? (1.f / bwk) : (1.f / (bwk * bwk));
    const bool lap = (k & 1);

    const int tx = t & 7, ty = t >> 3;
    float dsum = 0.f;
    // direct tile (zeroed where required)
    #pragma unroll
    for (int ii = 0; ii < 2; ii++) {
        const int lr = ty * 2 + ii;
        const int gi = i0 + lr;
        uint32_t pk[4];
        #pragma unroll
        for (int jj = 0; jj < 4; jj++) {
            const int lc = tx * 4 + jj;
            const int gj = j0 + lc;
            float dist = dsm[lr][lc];
            float kv = __expf(lap ? (-dist * iv) : (-dist * dist * iv));
            bool zr = (gi < NHALF) && (gj == gi + NHALF);
            if (zr) g_z[k][gi] = kv;
            if (gi == gj) dsum += kv;
            __nv_bfloat16 h = __float2bfloat16(kv);
            __nv_bfloat16 m = __float2bfloat16(kv - __bfloat162float(h));
            __nv_bfloat162 pr(h, m);
            uint32_t u = *(uint32_t*)&pr;
            pk[jj] = zr ? 0u : u;
        }
        const size_t base = (size_t)gi * NPTS + j0 + tx * 4;
        *(uint4*)&g_Kpk[k][base] = make_uint4(pk[0], pk[1], pk[2], pk[3]);
    }

    if (!diag) {
        // mirrored tile (un-zeroed): output row j0+rr, cols i0+cc0..+7
        const int rr = t >> 2;               // original column index 0..31
        const int cc0 = (t & 3) * 8;         // 8 consecutive original rows
        uint32_t v[8];
        #pragma unroll
        for (int q = 0; q < 8; q++) {
            float dist = dsm[cc0 + q][rr];
            float kv = __expf(lap ? (-dist * iv) : (-dist * dist * iv));
            __nv_bfloat16 h = __float2bfloat16(kv);
            __nv_bfloat16 m = __float2bfloat16(kv - __bfloat162float(h));
            __nv_bfloat162 pr(h, m);
            v[q] = *(uint32_t*)&pr;
        }
        const size_t base = (size_t)(j0 + rr) * NPTS + i0 + cc0;
        *(uint4*)&g_Kpk[k][base]     = make_uint4(v[0], v[1], v[2], v[3]);
        *(uint4*)&g_Kpk[k][base + 4] = make_uint4(v[4], v[5], v[6], v[7]);
    } else {
        float v = warpred(dsum);
        if ((t & 31) == 0) dsh[k][t >> 5] = v;
    }
    __syncthreads();
    if (diag && t == 0)
        g_DtP[k][bi] = dsh[k][0] + dsh[k][1] + dsh[k][2] + dsh[k][3];
}

// ---------------- kernel 2: mma.sync signed GEMM -> T partials -----------
// Single GEMM over doubled-k=1536 (hi,md interleaved in g_Kpk; mask duplicated).
// grid (6 n-tiles, 4 p-tiles, kk*4+quarter); 256 threads (8 warps: 4m x 2n).
// Each CTA: m=64 p-slots, n=128 K-rows, 6 chunks of 64 doubled-k.
__global__ void __launch_bounds__(256) k_mma() {
    __shared__ __align__(16) unsigned char As[2][64 * 128];    // 16 KB
    __shared__ __align__(16) unsigned char Bs[2][128 * 128];   // 32 KB
    const int nt = blockIdx.x, pt = blockIdx.y;
    const int kk = blockIdx.z >> 2, qt = blockIdx.z & 3;
    const int tid = threadIdx.x, w = tid >> 5, lane = tid & 31;
    const int wm = w & 3, wn = w >> 2;
    const uint32_t aBase = s2u(&As[0][0]);
    const uint32_t bBase = s2u(&Bs[0][0]);
    const __nv_bfloat16* __restrict__ KP = (const __nv_bfloat16*)g_Kpk[kk];

    float d[8][4] = {};

    auto load = [&](int ch, int buf) {
        const int a0 = (qt * 6 + ch) * 64;   // within doubled-k [0,1536)
        #pragma unroll 2
        for (int idx = tid; idx < 512; idx += 256) {        // A: 64 rows x 128B
            int r = idx >> 3, c = idx & 7;
            uint4 v = *(const uint4*)&g_mbf2[pt * 64 + r][a0 + c * 8];
            *(uint4*)&As[buf][r * 128 + ((c ^ (r & 7)) << 4)] = v;
        }
        #pragma unroll 4
        for (int idx = tid; idx < 1024; idx += 256) {       // B: 128 rows x 128B
            int r = idx >> 3, c = idx & 7;
            uint4 v = *(const uint4*)&KP[(size_t)(nt * 128 + r) * NPTS2 + a0 + c * 8];
            *(uint4*)&Bs[buf][r * 128 + ((c ^ (r & 7)) << 4)] = v;
        }
    };

    load(0, 0);
    __syncthreads();
    for (int ch = 0; ch < 6; ch++) {
        const int buf = ch & 1;
        if (ch + 1 < 6) load(ch + 1, buf ^ 1);
        #pragma unroll
        for (int ksq = 0; ksq < 4; ksq++) {
            uint32_t a[4];
            {
                int r = wm * 16 + (lane & 15);
                int c = ksq * 2 + (lane >> 4);
                uint32_t addr = aBase + buf * 8192 + r * 128 + ((c ^ (r & 7)) << 4);
                asm volatile("ldmatrix.sync.aligned.m8n8.x4.shared.b16 {%0,%1,%2,%3}, [%4];"
                             : "=r"(a[0]), "=r"(a[1]), "=r"(a[2]), "=r"(a[3]) : "r"(addr));
            }
            #pragma unroll
            for (int j = 0; j < 8; j++) {
                uint32_t b[2];
                int r = wn * 64 + j * 8 + (lane & 7);
                int c = ksq * 2 + ((lane >> 3) & 1);
                uint32_t addr = bBase + buf * 16384 + r * 128 + ((c ^ (r & 7)) << 4);
                asm volatile("ldmatrix.sync.aligned.m8n8.x2.shared.b16 {%0,%1}, [%2];"
                             : "=r"(b[0]), "=r"(b[1]) : "r"(addr));
                asm volatile("mma.sync.aligned.m16n8k16.row.col.f32.bf16.bf16.f32 "
                             "{%0,%1,%2,%3}, {%4,%5,%6,%7}, {%8,%9}, {%0,%1,%2,%3};"
                             : "+f"(d[j][0]), "+f"(d[j][1]), "+f"(d[j][2]), "+f"(d[j][3])
                             : "r"(a[0]), "r"(a[1]), "r"(a[2]), "r"(a[3]),
                               "r"(b[0]), "r"(b[1]));
            }
        }
        __syncthreads();
    }

    // epilogue: partial T[p] = sum_b s[p][b] * D'[p][b]
    const int lq = lane >> 2, lr = lane & 3;
    const int p0 = pt * 64 + wm * 16 + lq;
    const int p1 = p0 + 8;
    float part0 = 0.f, part1 = 0.f;
    #pragma unroll
    for (int j = 0; j < 8; j++) {
        int b0 = nt * 128 + wn * 64 + j * 8 + lr * 2;
        float m0 = __bfloat162float(g_mbf[p0][b0]);
        float m1 = __bfloat162float(g_mbf[p0][b0 + 1]);
        part0 += d[j][0] * m0 + d[j][1] * m1;
        float n0 = __bfloat162float(g_mbf[p1][b0]);
        float n1 = __bfloat162float(g_mbf[p1][b0 + 1]);
        part1 += d[j][2] * n0 + d[j][3] * n1;
    }
    part0 += __shfl_xor_sync(0xffffffffu, part0, 1);
    part0 += __shfl_xor_sync(0xffffffffu, part0, 2);
    part1 += __shfl_xor_sync(0xffffffffu, part1, 1);
    part1 += __shfl_xor_sync(0xffffffffu, part1, 2);
    if (lr == 0) {
        const int sub = qt * 12 + nt * 2 + wn;
        g_part[kk][sub][p0] = part0;
        g_part[kk][sub][p1] = part1;
    }
}

// ---------------- kernel 3: phase 2 per-(slot, kernel) combine -----------
// Ub = (C1/4)*T + sum_{a in A} (+-z[a])/nm + C4*cross + (S*CS - Dt/nn)
__global__ void __launch_bounds__(128) k_phase2(const int* __restrict__ perms,
                                                float* __restrict__ out) {
    const int p = blockIdx.x;          // 0..200
    const int kk = blockIdx.y;
    const int tid = threadIdx.x;       // 128
    __shared__ float sm[3][4];
    const bool ident = (p == NPER);

    const uint32_t* __restrict__ Kp = g_Kpk[kk];
    const float* __restrict__ Zc = g_z[kk];

    float t1 = 0.f, cr = 0.f, aux = 0.f;
    #pragma unroll
    for (int it = 0; it < 3; it++) {
        int j = tid + it * 128;
        int a = ident ? j : __ldg(&perms[p * NPTS + j]);
        int b = ident ? (NHALF + j) : __ldg(&perms[p * NPTS + NHALF + j]);
        t1 += (a < NHALF) ? (INV_NM * Zc[a]) : (-INV_NM * Zc[a - NHALF]);
        uint32_t wv = __ldg(&Kp[a * NPTS + b]);
        __nv_bfloat162 v = *reinterpret_cast<__nv_bfloat162*>(&wv);
        cr += __bfloat162float(v.x) + __bfloat162float(v.y);
    }
    if (tid < 48) {
        t1 += C14 * g_part[kk][tid][p];
        aux += CS * g_part[kk][tid][201];          // S*CS partials
    }
    if (tid >= 64 && tid < 88)
        aux -= INV_NN * g_DtP[kk][tid - 64];       // -Dt/nn partials

    float r1 = warpred(t1), r2 = warpred(cr), r3 = warpred(aux);
    if ((tid & 31) == 0) {
        sm[0][tid >> 5] = r1; sm[1][tid >> 5] = r2; sm[2][tid >> 5] = r3;
    }
    __syncthreads();
    if (tid == 0) {
        float T1 = sm[0][0] + sm[0][1] + sm[0][2] + sm[0][3];
        float CR = sm[1][0] + sm[1][1] + sm[1][2] + sm[1][3];
        float AX = sm[2][0] + sm[2][1] + sm[2][2] + sm[2][3];
        float Ub = T1 + C4 * CR + AX;
        int idx = ident ? (kk * (NPER + 1)) : (kk * (NPER + 1) + 1 + p);
        out[idx] = Ub;
    }
}

// ---------------- launch ----------------
extern "C" void kernel_launch(void* const* d_in, const int* in_sizes, int n_in,
                              void* d_out, int out_size) {
    const float* X     = (const float*)d_in[0];
    const float* Y     = (const float*)d_in[1];
    const float* bw    = (const float*)d_in[2];
    const int*   perms = (const int*)d_in[3];
    float* out = (float*)d_out;

    k_pairmask<<<NSLOT + NTRI, 512>>>(X, Y, bw, perms);
    k_mma<<<dim3(6, 4, 16), 256>>>();
    k_phase2<<<dim3(NPER + 1, NKER), 128>>>(perms, out);
}

// round 16
// speedup vs baseline: 1.3781x; 1.0625x over previous
#include <cuda_runtime.h>
#include <cuda_bf16.h>
#include <math.h>
#include <cstdint>

#define NPTS  768
#define NPTS2 1536    // doubled-k (hi,md interleaved)
#define NHALF 384
#define DDIM  64
#define NPER  200
#define NKER  4
#define NSLOT 202     // 200 perms + identity(200) + all-ones(201)
#define PSLOTS 256    // padded p dimension (4 tiles of 64)
#define NTRI  300     // 24*25/2 triangle blocks of 32x32

#define INV_NN (1.0f/147072.0f)    // 384*383
#define INV_NM (1.0f/147456.0f)    // 384*384
#define C1 (2.0f*INV_NN + 2.0f*INV_NM)
#define C14 (0.25f*C1)
#define C4 (2.0f*INV_NM)
// 0.5*(1/nn - 1/nm), analytic (no cancellation)
#define CS ((float)(0.5*(1.0/147072.0 - 1.0/147456.0)))

// ---------------- scratch (device globals; zero-initialized) -------------
__device__ uint32_t      g_Kpk[NKER][NPTS * NPTS];   // 9 MB: (hi,md) bf16 pairs
__device__ __nv_bfloat16 g_mbf[PSLOTS][NPTS];        // signed mask rows
__device__ __nv_bfloat16 g_mbf2[PSLOTS][NPTS2];      // duplicated mask (doubled-k)
__device__ float g_z[NKER][NHALF];                   // K[i][384+i] pre-zero value
__device__ float g_DtP[NKER][24];                    // diag partials per diag block
__device__ float g_part[NKER][48][PSLOTS];           // T partials (4 kquarter x 12 subtiles)

// ---------------- helpers ----------------
__device__ __forceinline__ float warpred(float v) {
    #pragma unroll
    for (int o = 16; o > 0; o >>= 1) v += __shfl_down_sync(0xffffffffu, v, o);
    return v;
}

__device__ __forceinline__ uint32_t s2u(const void* p) {
    uint32_t r;
    asm("{ .reg .u64 t; cvta.to.shared.u64 t, %1; cvt.u32.u64 %0, t; }"
        : "=r"(r) : "l"(p));
    return r;
}

#define GROUP_BAR(id) asm volatile("bar.sync %0, 128;" :: "r"(id) : "memory")

// ---------------- kernel 1: symmetric pairK (blocks 0..299) + mask -------
// triangle blocks: one 32x32 tile, 4 kernel fns via 128-thread warp groups.
__global__ void __launch_bounds__(512) k_pairmask(const float* __restrict__ X,
                                                  const float* __restrict__ Y,
                                                  const float* __restrict__ bw,
                                                  const int* __restrict__ perms) {
    const int blk = blockIdx.x;
    const int tid = threadIdx.x;

    if (blk >= NTRI) {                      // ---- mask part ----
        const int p = blk - NTRI;
        for (int j = tid; j < NPTS; j += 512) {
            __nv_bfloat16 v;
            int a;
            if (p < NPER) {
                v = __float2bfloat16(j < NHALF ? 1.f : -1.f);
                a = perms[p * NPTS + j];
            } else if (p == NPER) {
                v = __float2bfloat16(j < NHALF ? 1.f : -1.f);
                a = j;
            } else {
                v = __float2bfloat16(1.f);
                a = j;
            }
            g_mbf[p][a] = v;
            __nv_bfloat162 vv(v, v);
            *(__nv_bfloat162*)&g_mbf2[p][2 * a] = vv;
        }
        return;
    }

    // ---- triangle decode ----
    int t2 = blk, bi = 0;
    while (t2 >= 24 - bi) { t2 -= 24 - bi; bi++; }
    const int bj = bi + t2;
    const int i0 = bi * 32, j0 = bj * 32;
    const bool diag = (bi == bj);

    // Z tiles (68-float rows: every float4 slot 16B-aligned). After the dot
    // phase Zi/Zj are dead; the packed-word staging arrays alias them.
    __shared__ __align__(16) char sbuf[2 * 32 * 68 * 4];   // 34816 B
    float (*Zi)[68] = (float(*)[68])sbuf;
    float (*Zj)[68] = (float(*)[68])(sbuf + 32 * 68 * 4);
    uint32_t (*usm)[32][33] = (uint32_t(*)[32][33])sbuf;   // 4*32*33*4 = 16896 B
    __shared__ float sq[64];                 // sqi[0..31], sqj[32..63]
    __shared__ float dsm[32][33];            // distances
    __shared__ float dsh[4][4];              // diag partials [group][warp]

    // load Z tiles (float4 vectorized; 512 threads = 32 rows x 16 quads)
    {
        const int r = tid >> 4, q = tid & 15;
        const int gi = i0 + r;
        const float4* srcI = (const float4*)((gi < NHALF) ? (X + gi * DDIM)
                                                          : (Y + (gi - NHALF) * DDIM));
        *(float4*)&Zi[r][q * 4] = srcI[q];
        const int gj = j0 + r;
        const float4* srcJ = (const float4*)((gj < NHALF) ? (X + gj * DDIM)
                                                          : (Y + (gj - NHALF) * DDIM));
        *(float4*)&Zj[r][q * 4] = srcJ[q];
    }
    __syncthreads();

    if (tid < 64) {
        const float* src = (tid < 32) ? &Zi[tid][0] : &Zj[tid - 32][0];
        float s = 0.f;
        #pragma unroll
        for (int d = 0; d < 64; d++) { float v = src[d]; s += v * v; }
        sq[tid] = s;
    }
    __syncthreads();

    // dot phase: 512 threads, each 2 elements (row dty; cols dtx, dtx+16)
    {
        const int dty = tid >> 4, dtx = tid & 15;
        float acc0 = 0.f, acc1 = 0.f;
        #pragma unroll
        for (int q = 0; q < 16; q++) {
            float4 a  = *(const float4*)&Zi[dty][q * 4];
            float4 b0 = *(const float4*)&Zj[dtx][q * 4];
            float4 b1 = *(const float4*)&Zj[dtx + 16][q * 4];
            acc0 += a.x * b0.x + a.y * b0.y + a.z * b0.z + a.w * b0.w;
            acc1 += a.x * b1.x + a.y * b1.y + a.z * b1.z + a.w * b1.w;
        }
        float si = sq[dty];
        float d20 = fmaxf(si + sq[32 + dtx] - 2.f * acc0, 0.f);
        float d21 = fmaxf(si + sq[32 + dtx + 16] - 2.f * acc1, 0.f);
        dsm[dty][dtx]      = sqrtf(d20 + 1e-12f);
        dsm[dty][dtx + 16] = sqrtf(d21 + 1e-12f);
    }
    __syncthreads();   // Zi/Zj dead from here; usm aliases them

    // kernel phase: group g (128 threads) handles kernel function g
    const int k = tid >> 7;                  // 0..3
    const int t = tid & 127;
    const float bwk = bw[k];
    const float iv = (k & 1) ? (1.f / bwk) : (1.f / (bwk * bwk));
    const bool lap = (k & 1);

    const int tx = t & 7, ty = t >> 3;
    float dsum = 0.f;
    // direct tile: compute, store (zeroed), stage un-zeroed words in usm
    #pragma unroll
    for (int ii = 0; ii < 2; ii++) {
        const int lr = ty * 2 + ii;
        const int gi = i0 + lr;
        uint32_t pk[4];
        #pragma unroll
        for (int jj = 0; jj < 4; jj++) {
            const int lc = tx * 4 + jj;
            const int gj = j0 + lc;
            float dist = dsm[lr][lc];
            float kv = __expf(lap ? (-dist * iv) : (-dist * dist * iv));
            bool zr = (gi < NHALF) && (gj == gi + NHALF);
            if (zr) g_z[k][gi] = kv;
            if (gi == gj) dsum += kv;
            __nv_bfloat16 h = __float2bfloat16(kv);
            __nv_bfloat16 m = __float2bfloat16(kv - __bfloat162float(h));
            __nv_bfloat162 pr(h, m);
            uint32_t u = *(uint32_t*)&pr;
            usm[k][lr][lc] = u;
            pk[jj] = zr ? 0u : u;
        }
        const size_t base = (size_t)gi * NPTS + j0 + tx * 4;
        *(uint4*)&g_Kpk[k][base] = make_uint4(pk[0], pk[1], pk[2], pk[3]);
    }

    GROUP_BAR(k + 1);   // group-local: staging complete

    if (!diag) {
        // mirrored tile (un-zeroed): pure transposed copy from usm
        const int rr = t >> 2;               // original column index 0..31
        const int cc0 = (t & 3) * 8;         // 8 consecutive original rows
        uint32_t v[8];
        #pragma unroll
        for (int q = 0; q < 8; q++) v[q] = usm[k][cc0 + q][rr];
        const size_t base = (size_t)(j0 + rr) * NPTS + i0 + cc0;
        *(uint4*)&g_Kpk[k][base]     = make_uint4(v[0], v[1], v[2], v[3]);
        *(uint4*)&g_Kpk[k][base + 4] = make_uint4(v[4], v[5], v[6], v[7]);
    } else {
        float v = warpred(dsum);
        if ((t & 31) == 0) dsh[k][t >> 5] = v;
        GROUP_BAR(k + 1);
        if (t == 0)
            g_DtP[k][bi] = dsh[k][0] + dsh[k][1] + dsh[k][2] + dsh[k][3];
    }
}

// ---------------- kernel 2: mma.sync signed GEMM -> T partials -----------
// Single GEMM over doubled-k=1536 (hi,md interleaved in g_Kpk; mask duplicated).
// grid (6 n-tiles, 4 p-tiles, kk*4+quarter); 256 threads (8 warps: 4m x 2n).
__global__ void __launch_bounds__(256) k_mma() {
    __shared__ __align__(16) unsigned char As[2][64 * 128];    // 16 KB
    __shared__ __align__(16) unsigned char Bs[2][128 * 128];   // 32 KB
    const int nt = blockIdx.x, pt = blockIdx.y;
    const int kk = blockIdx.z >> 2, qt = blockIdx.z & 3;
    const int tid = threadIdx.x, w = tid >> 5, lane = tid & 31;
    const int wm = w & 3, wn = w >> 2;
    const uint32_t aBase = s2u(&As[0][0]);
    const uint32_t bBase = s2u(&Bs[0][0]);
    const __nv_bfloat16* __restrict__ KP = (const __nv_bfloat16*)g_Kpk[kk];

    float d[8][4] = {};

    auto load = [&](int ch, int buf) {
        const int a0 = (qt * 6 + ch) * 64;   // within doubled-k [0,1536)
        #pragma unroll 2
        for (int idx = tid; idx < 512; idx += 256) {        // A: 64 rows x 128B
            int r = idx >> 3, c = idx & 7;
            uint4 v = *(const uint4*)&g_mbf2[pt * 64 + r][a0 + c * 8];
            *(uint4*)&As[buf][r * 128 + ((c ^ (r & 7)) << 4)] = v;
        }
        #pragma unroll 4
        for (int idx = tid; idx < 1024; idx += 256) {       // B: 128 rows x 128B
            int r = idx >> 3, c = idx & 7;
            uint4 v = *(const uint4*)&KP[(size_t)(nt * 128 + r) * NPTS2 + a0 + c * 8];
            *(uint4*)&Bs[buf][r * 128 + ((c ^ (r & 7)) << 4)] = v;
        }
    };

    load(0, 0);
    __syncthreads();
    for (int ch = 0; ch < 6; ch++) {
        const int buf = ch & 1;
        if (ch + 1 < 6) load(ch + 1, buf ^ 1);
        #pragma unroll
        for (int ksq = 0; ksq < 4; ksq++) {
            uint32_t a[4];
            {
                int r = wm * 16 + (lane & 15);
                int c = ksq * 2 + (lane >> 4);
                uint32_t addr = aBase + buf * 8192 + r * 128 + ((c ^ (r & 7)) << 4);
                asm volatile("ldmatrix.sync.aligned.m8n8.x4.shared.b16 {%0,%1,%2,%3}, [%4];"
                             : "=r"(a[0]), "=r"(a[1]), "=r"(a[2]), "=r"(a[3]) : "r"(addr));
            }
            #pragma unroll
            for (int j = 0; j < 8; j++) {
                uint32_t b[2];
                int r = wn * 64 + j * 8 + (lane & 7);
                int c = ksq * 2 + ((lane >> 3) & 1);
                uint32_t addr = bBase + buf * 16384 + r * 128 + ((c ^ (r & 7)) << 4);
                asm volatile("ldmatrix.sync.aligned.m8n8.x2.shared.b16 {%0,%1}, [%2];"
                             : "=r"(b[0]), "=r"(b[1]) : "r"(addr));
                asm volatile("mma.sync.aligned.m16n8k16.row.col.f32.bf16.bf16.f32 "
                             "{%0,%1,%2,%3}, {%4,%5,%6,%7}, {%8,%9}, {%0,%1,%2,%3};"
                             : "+f"(d[j][0]), "+f"(d[j][1]), "+f"(d[j][2]), "+f"(d[j][3])
                             : "r"(a[0]), "r"(a[1]), "r"(a[2]), "r"(a[3]),
                               "r"(b[0]), "r"(b[1]));
            }
        }
        __syncthreads();
    }

    // epilogue: partial T[p] = sum_b s[p][b] * D'[p][b]
    const int lq = lane >> 2, lr = lane & 3;
    const int p0 = pt * 64 + wm * 16 + lq;
    const int p1 = p0 + 8;
    float part0 = 0.f, part1 = 0.f;
    #pragma unroll
    for (int j = 0; j < 8; j++) {
        int b0 = nt * 128 + wn * 64 + j * 8 + lr * 2;
        float m0 = __bfloat162float(g_mbf[p0][b0]);
        float m1 = __bfloat162float(g_mbf[p0][b0 + 1]);
        part0 += d[j][0] * m0 + d[j][1] * m1;
        float n0 = __bfloat162float(g_mbf[p1][b0]);
        float n1 = __bfloat162float(g_mbf[p1][b0 + 1]);
        part1 += d[j][2] * n0 + d[j][3] * n1;
    }
    part0 += __shfl_xor_sync(0xffffffffu, part0, 1);
    part0 += __shfl_xor_sync(0xffffffffu, part0, 2);
    part1 += __shfl_xor_sync(0xffffffffu, part1, 1);
    part1 += __shfl_xor_sync(0xffffffffu, part1, 2);
    if (lr == 0) {
        const int sub = qt * 12 + nt * 2 + wn;
        g_part[kk][sub][p0] = part0;
        g_part[kk][sub][p1] = part1;
    }
}

// ---------------- kernel 3: phase 2 per-(slot, kernel) combine -----------
// Ub = (C1/4)*T + sum_{a in A} (+-z[a])/nm + C4*cross + (S*CS - Dt/nn)
__global__ void __launch_bounds__(128) k_phase2(const int* __restrict__ perms,
                                                float* __restrict__ out) {
    const int p = blockIdx.x;          // 0..200
    const int kk = blockIdx.y;
    const int tid = threadIdx.x;       // 128
    __shared__ float sm[3][4];
    const bool ident = (p == NPER);

    const uint32_t* __restrict__ Kp = g_Kpk[kk];
    const float* __restrict__ Zc = g_z[kk];

    float t1 = 0.f, cr = 0.f, aux = 0.f;
    #pragma unroll
    for (int it = 0; it < 3; it++) {
        int j = tid + it * 128;
        int a = ident ? j : __ldg(&perms[p * NPTS + j]);
        int b = ident ? (NHALF + j) : __ldg(&perms[p * NPTS + NHALF + j]);
        t1 += (a < NHALF) ? (INV_NM * Zc[a]) : (-INV_NM * Zc[a - NHALF]);
        uint32_t wv = __ldg(&Kp[a * NPTS + b]);
        __nv_bfloat162 v = *reinterpret_cast<__nv_bfloat162*>(&wv);
        cr += __bfloat162float(v.x) + __bfloat162float(v.y);
    }
    if (tid < 48) {
        t1 += C14 * g_part[kk][tid][p];
        aux += CS * g_part[kk][tid][201];          // S*CS partials
    }
    if (tid >= 64 && tid < 88)
        aux -= INV_NN * g_DtP[kk][tid - 64];       // -Dt/nn partials

    float r1 = warpred(t1), r2 = warpred(cr), r3 = warpred(aux);
    if ((tid & 31) == 0) {
        sm[0][tid >> 5] = r1; sm[1][tid >> 5] = r2; sm[2][tid >> 5] = r3;
    }
    __syncthreads();
    if (tid == 0) {
        float T1 = sm[0][0] + sm[0][1] + sm[0][2] + sm[0][3];
        float CR = sm[1][0] + sm[1][1] + sm[1][2] + sm[1][3];
        float AX = sm[2][0] + sm[2][1] + sm[2][2] + sm[2][3];
        float Ub = T1 + C4 * CR + AX;
        int idx = ident ? (kk * (NPER + 1)) : (kk * (NPER + 1) + 1 + p);
        out[idx] = Ub;
    }
}

// ---------------- launch ----------------
extern "C" void kernel_launch(void* const* d_in, const int* in_sizes, int n_in,
                              void* d_out, int out_size) {
    const float* X     = (const float*)d_in[0];
    const float* Y     = (const float*)d_in[1];
    const float* bw    = (const float*)d_in[2];
    const int*   perms = (const int*)d_in[3];
    float* out = (float*)d_out;

    k_pairmask<<<NTRI + NSLOT, 512>>>(X, Y, bw, perms);
    k_mma<<<dim3(6, 4, 16), 256>>>();
    k_phase2<<<dim3(NPER + 1, NKER), 128>>>(perms, out);
}